// round 16
// baseline (speedup 1.0000x reference)
#include <cuda_runtime.h>
#include <cuda_bf16.h>
#include <cstdint>

#define B_  2
#define S_  2048
#define D_  1024
#define H_  16
#define KS_ 64
#define NEG_BIG (-1.0e9f)

#define NTOK ((size_t)B_ * S_ * D_)

#define F_ACT   (NTOK / 2)
#define F_W     ((size_t)D_ * D_ / 2)
__device__ __align__(16) float g_scratch[10 * F_ACT + 8 * F_W];

typedef uint32_t u32;

// ============================ helpers ======================================
__device__ __forceinline__ u32 smem_u32(const void* p) {
    u32 a;
    asm("{ .reg .u64 t; cvta.to.shared.u64 t, %1; cvt.u32.u64 %0, t; }"
        : "=r"(a) : "l"(p));
    return a;
}
__device__ __forceinline__ void cp_async16(u32 saddr, const void* gaddr) {
    asm volatile("cp.async.cg.shared.global [%0], [%1], 16;"
                 :: "r"(saddr), "l"(gaddr) : "memory");
}
__device__ __forceinline__ void cp_commit() {
    asm volatile("cp.async.commit_group;" ::: "memory");
}
template <int N>
__device__ __forceinline__ void cp_wait() {
    asm volatile("cp.async.wait_group %0;" :: "n"(N) : "memory");
}
__device__ __forceinline__ void mma16816(float* d, u32 a0, u32 a1,
                                         u32 a2, u32 a3, u32 b0, u32 b1) {
    asm volatile(
        "mma.sync.aligned.m16n8k16.row.col.f32.bf16.bf16.f32 "
        "{%0,%1,%2,%3}, {%4,%5,%6,%7}, {%8,%9}, {%0,%1,%2,%3};"
        : "+f"(d[0]), "+f"(d[1]), "+f"(d[2]), "+f"(d[3])
        : "r"(a0), "r"(a1), "r"(a2), "r"(a3), "r"(b0), "r"(b1));
}
__device__ __forceinline__ void ldsm_x2_t(u32& r0, u32& r1, u32 a) {
    asm volatile("ldmatrix.sync.aligned.m8n8.x2.trans.shared.b16 {%0,%1}, [%2];"
                 : "=r"(r0), "=r"(r1) : "r"(a));
}
__device__ __forceinline__ void ldsm_x4(u32& r0, u32& r1, u32& r2, u32& r3, u32 a) {
    asm volatile("ldmatrix.sync.aligned.m8n8.x4.shared.b16 {%0,%1,%2,%3}, [%4];"
                 : "=r"(r0), "=r"(r1), "=r"(r2), "=r"(r3) : "r"(a));
}
__device__ __forceinline__ u32 f2bf_bits(float x) {
    u32 u = __float_as_uint(x);
    return (u + 0x7FFFu + ((u >> 16) & 1u)) >> 16;
}
__device__ __forceinline__ void pack_pair(float p0, float p1, u32& hi, u32& lo) {
    asm("cvt.rn.bf16x2.f32 %0, %1, %2;" : "=r"(hi) : "f"(p1), "f"(p0));
    float h0 = __uint_as_float(hi << 16);
    float h1 = __uint_as_float(hi & 0xffff0000u);
    asm("cvt.rn.bf16x2.f32 %0, %1, %2;" : "=r"(lo) : "f"(p1 - h1), "f"(p0 - h0));
}
__device__ __forceinline__ float exp_fast(float x) {
    x = fmaxf(x, -87.3f);
    float y = x * 1.44269504089f;
    float n = rintf(y);
    float f = y - n;
    float p = 1.33336498402e-3f;
    p = fmaf(p, f, 9.61793571616e-3f);
    p = fmaf(p, f, 5.55043442248e-2f);
    p = fmaf(p, f, 2.40226506959e-1f);
    p = fmaf(p, f, 6.93147180560e-1f);
    p = fmaf(p, f, 1.0f);
    return __int_as_float(__float_as_int(p) + (((int)n) << 23));
}

// ======================= conversion kernels ================================
__global__ void conv_act2(const float* __restrict__ x0, __nv_bfloat16* __restrict__ h0,
                          __nv_bfloat16* __restrict__ l0,
                          const float* __restrict__ x1, __nv_bfloat16* __restrict__ h1,
                          __nv_bfloat16* __restrict__ l1, int n) {
    const float* x = blockIdx.z ? x1 : x0;
    __nv_bfloat16* h = blockIdx.z ? h1 : h0;
    __nv_bfloat16* l = blockIdx.z ? l1 : l0;
    int i = blockIdx.x * blockDim.x + threadIdx.x;
    int i4 = i * 4;
    if (i4 >= n) return;
    float4 v = *(const float4*)(x + i4);
    float vs[4] = {v.x, v.y, v.z, v.w};
    __nv_bfloat16 hh[4], ll[4];
    #pragma unroll
    for (int j = 0; j < 4; j++) {
        __nv_bfloat16 hi = __float2bfloat16_rn(vs[j]);
        float r = vs[j] - __bfloat162float(hi);
        hh[j] = hi;
        ll[j] = __float2bfloat16_rn(r);
    }
    __nv_bfloat162* H2 = (__nv_bfloat162*)(h + i4);
    __nv_bfloat162* L2 = (__nv_bfloat162*)(l + i4);
    H2[0] = __nv_bfloat162(hh[0], hh[1]);
    H2[1] = __nv_bfloat162(hh[2], hh[3]);
    L2[0] = __nv_bfloat162(ll[0], ll[1]);
    L2[1] = __nv_bfloat162(ll[2], ll[3]);
}

__global__ void conv_w4(const float* __restrict__ W0, const float* __restrict__ W1,
                        const float* __restrict__ W2, const float* __restrict__ W3,
                        __nv_bfloat16* __restrict__ T0h, __nv_bfloat16* __restrict__ T0l,
                        __nv_bfloat16* __restrict__ T1h, __nv_bfloat16* __restrict__ T1l,
                        __nv_bfloat16* __restrict__ T2h, __nv_bfloat16* __restrict__ T2l,
                        __nv_bfloat16* __restrict__ T3h, __nv_bfloat16* __restrict__ T3l) {
    __shared__ float t[32][33];
    const float* W;
    __nv_bfloat16 *Th, *Tl;
    switch (blockIdx.z) {
        case 0: W = W0; Th = T0h; Tl = T0l; break;
        case 1: W = W1; Th = T1h; Tl = T1l; break;
        case 2: W = W2; Th = T2h; Tl = T2l; break;
        default: W = W3; Th = T3h; Tl = T3l; break;
    }
    int n0 = blockIdx.x * 32, k0 = blockIdx.y * 32;
    int tx = threadIdx.x, ty = threadIdx.y;
    for (int r = ty; r < 32; r += 8)
        t[r][tx] = W[(size_t)(k0 + r) * D_ + n0 + tx];
    __syncthreads();
    for (int r = ty; r < 32; r += 8) {
        float x = t[tx][r];
        __nv_bfloat16 hi = __float2bfloat16_rn(x);
        float res = x - __bfloat162float(hi);
        size_t o = (size_t)(n0 + r) * D_ + k0 + tx;
        Th[o] = hi;
        Tl[o] = __float2bfloat16_rn(res);
    }
}

// ======================= HMMA GEMM core (ldsm fragments) ===================
#define GROW   80
#define GTILE  (128 * GROW)
#define GSTAGE (4 * GTILE)
#define GSMEM  (2 * GSTAGE)

#define GEMM_BODY(ACC)                                                          \
    const u32 sb = smem_u32(smem);                                              \
    const int tid  = threadIdx.x;                                               \
    const int lane = tid & 31;                                                  \
    const int wid  = tid >> 5;                                                  \
    const int wm   = wid >> 2;                                                  \
    const int wn   = wid & 3;                                                   \
    const int g    = lane >> 2;                                                 \
    const int q    = lane & 3;                                                  \
    const int l7   = lane & 7;                                                  \
    const int sel  = lane >> 3;                                                 \
    const int n0 = blockIdx.x * 128;                                            \
    const int m0 = blockIdx.y * 128;                                            \
    const int cid0 = tid * 2;                                                   \
    const int row0 = cid0 >> 2;                                                 \
    const int cc0  = (cid0 & 3) * 8;                                            \
    const int row1 = (cid0 + 1) >> 2;                                           \
    const int cc1  = ((cid0 + 1) & 3) * 8;                                      \
    const int NK = D_ / 32;                                                     \
    {                                                                           \
        u32 s = sb;                                                             \
        cp_async16(s + 0 * GTILE + row0 * GROW + (cc0 & 31) * 2, Ah + (size_t)(m0 + row0) * D_ + cc0); \
        cp_async16(s + 0 * GTILE + row1 * GROW + (cc1 & 31) * 2, Ah + (size_t)(m0 + row1) * D_ + cc1); \
        cp_async16(s + 1 * GTILE + row0 * GROW + (cc0 & 31) * 2, Al + (size_t)(m0 + row0) * D_ + cc0); \
        cp_async16(s + 1 * GTILE + row1 * GROW + (cc1 & 31) * 2, Al + (size_t)(m0 + row1) * D_ + cc1); \
        cp_async16(s + 2 * GTILE + row0 * GROW + (cc0 & 31) * 2, Bh + (size_t)(n0 + row0) * D_ + cc0); \
        cp_async16(s + 2 * GTILE + row1 * GROW + (cc1 & 31) * 2, Bh + (size_t)(n0 + row1) * D_ + cc1); \
        cp_async16(s + 3 * GTILE + row0 * GROW + (cc0 & 31) * 2, Bl + (size_t)(n0 + row0) * D_ + cc0); \
        cp_async16(s + 3 * GTILE + row1 * GROW + (cc1 & 31) * 2, Bl + (size_t)(n0 + row1) * D_ + cc1); \
        cp_commit();                                                            \
    }                                                                           \
    for (int ks = 0; ks < NK; ks++) {                                           \
        if (ks + 1 < NK) {                                                      \
            int k0 = (ks + 1) * 32;                                             \
            u32 s = sb + ((ks + 1) & 1) * GSTAGE;                               \
            cp_async16(s + 0 * GTILE + row0 * GROW + (cc0 & 31) * 2, Ah + (size_t)(m0 + row0) * D_ + k0 + cc0); \
            cp_async16(s + 0 * GTILE + row1 * GROW + (cc1 & 31) * 2, Ah + (size_t)(m0 + row1) * D_ + k0 + cc1); \
            cp_async16(s + 1 * GTILE + row0 * GROW + (cc0 & 31) * 2, Al + (size_t)(m0 + row0) * D_ + k0 + cc0); \
            cp_async16(s + 1 * GTILE + row1 * GROW + (cc1 & 31) * 2, Al + (size_t)(m0 + row1) * D_ + k0 + cc1); \
            cp_async16(s + 2 * GTILE + row0 * GROW + (cc0 & 31) * 2, Bh + (size_t)(n0 + row0) * D_ + k0 + cc0); \
            cp_async16(s + 2 * GTILE + row1 * GROW + (cc1 & 31) * 2, Bh + (size_t)(n0 + row1) * D_ + k0 + cc1); \
            cp_async16(s + 3 * GTILE + row0 * GROW + (cc0 & 31) * 2, Bl + (size_t)(n0 + row0) * D_ + k0 + cc0); \
            cp_async16(s + 3 * GTILE + row1 * GROW + (cc1 & 31) * 2, Bl + (size_t)(n0 + row1) * D_ + k0 + cc1); \
            cp_commit();                                                        \
            cp_wait<1>();                                                       \
        } else {                                                                \
            cp_wait<0>();                                                       \
        }                                                                       \
        __syncthreads();                                                        \
        u32 st_u  = sb + (ks & 1) * GSTAGE;                                     \
        u32 sAh_u = st_u;                                                       \
        u32 sBh_u = st_u + 2 * GTILE;                                           \
        _Pragma("unroll")                                                       \
        for (int kk = 0; kk < 32; kk += 16) {                                   \
            u32 bh[4][2], bl[4][2];                                             \
            _Pragma("unroll")                                                   \
            for (int j = 0; j < 4; j++) {                                       \
                u32 baddr = sBh_u + (u32)((wn * 32 + j * 8 + l7) * GROW         \
                            + (sel & 1) * 16 + (sel >> 1) * GTILE + kk * 2);    \
                ldsm_x4(bh[j][0], bh[j][1], bl[j][0], bl[j][1], baddr);         \
            }                                                                   \
            _Pragma("unroll")                                                   \
            for (int i = 0; i < 4; i++) {                                       \
                int m = wm * 64 + i * 16;                                       \
                u32 aaddr = sAh_u + (u32)((m + l7 + (sel & 1) * 8) * GROW       \
                            + (kk + (sel >> 1) * 8) * 2);                       \
                u32 ah0, ah1, ah2, ah3, al0, al1, al2, al3;                     \
                ldsm_x4(ah0, ah1, ah2, ah3, aaddr);                             \
                ldsm_x4(al0, al1, al2, al3, aaddr + GTILE);                     \
                _Pragma("unroll")                                               \
                for (int j = 0; j < 4; j++) {                                   \
                    mma16816(ACC[i][j], ah0, ah1, ah2, ah3, bh[j][0], bh[j][1]);\
                    mma16816(ACC[i][j], ah0, ah1, ah2, ah3, bl[j][0], bl[j][1]);\
                    mma16816(ACC[i][j], al0, al1, al2, al3, bh[j][0], bh[j][1]);\
                }                                                               \
            }                                                                   \
        }                                                                       \
        __syncthreads();                                                        \
    }

// Final projection + FUSED align fixup tail (overlaps fixup's DRAM traffic
// with other blocks' tensor mainloops; fixup math identical to R12-15).
__global__ void __launch_bounds__(256) gemm_mma(
    const __nv_bfloat16* __restrict__ Ah, const __nv_bfloat16* __restrict__ Al,
    const __nv_bfloat16* __restrict__ Bh, const __nv_bfloat16* __restrict__ Bl,
    const float* __restrict__ bias, float* __restrict__ C,
    float* __restrict__ align, const float* __restrict__ mu,
    const float* __restrict__ mfin, const float* __restrict__ isv) {
    extern __shared__ char smem[];
    float acc[4][4][4] = {};
    GEMM_BODY(acc)
    #pragma unroll
    for (int i = 0; i < 4; i++) {
        int row = m0 + wm * 64 + i * 16;
        #pragma unroll
        for (int j = 0; j < 4; j++) {
            int col = n0 + wn * 32 + j * 8 + 2 * q;
            float b0 = __ldg(bias + col);
            float b1 = __ldg(bias + col + 1);
            float2 v0 = make_float2(acc[i][j][0] + b0, acc[i][j][1] + b1);
            float2 v1 = make_float2(acc[i][j][2] + b0, acc[i][j][3] + b1);
            *(float2*)&C[(size_t)(row + g) * D_ + col]     = v0;
            *(float2*)&C[(size_t)(row + g + 8) * D_ + col] = v1;
        }
    }

    // ---- fused fixup: this block rescales 256 align rows ----
    {
        size_t rbase = (size_t)(blockIdx.y * gridDim.x + blockIdx.x) * 256;
        #pragma unroll 4
        for (int i = tid; i < 256 * 512; i += 256) {
            int r  = i >> 9;                   // 512 float4 per row
            int c4 = i & 511;
            size_t R = rbase + r;
            float f = exp_fast(__ldg(mu + R * 32 + (c4 >> 4)) - __ldg(mfin + R))
                      * __ldg(isv + R);
            float4* p = (float4*)&align[R * S_ + (size_t)c4 * 4];
            float4 v = *p;
            v.x *= f; v.y *= f; v.z *= f; v.w *= f;
            *p = v;
        }
    }
}

__global__ void __launch_bounds__(256) gemm_split3(
    const __nv_bfloat16* __restrict__ Aq_h, const __nv_bfloat16* __restrict__ Aq_l,
    const __nv_bfloat16* __restrict__ Av_h, const __nv_bfloat16* __restrict__ Av_l,
    const __nv_bfloat16* __restrict__ Wq_h, const __nv_bfloat16* __restrict__ Wq_l,
    const __nv_bfloat16* __restrict__ Wk_h, const __nv_bfloat16* __restrict__ Wk_l,
    const __nv_bfloat16* __restrict__ Wv_h, const __nv_bfloat16* __restrict__ Wv_l,
    const float* __restrict__ bq, const float* __restrict__ bk, const float* __restrict__ bv,
    __nv_bfloat16* __restrict__ Q_h, __nv_bfloat16* __restrict__ Q_l,
    __nv_bfloat16* __restrict__ K_h, __nv_bfloat16* __restrict__ K_l,
    __nv_bfloat16* __restrict__ V_h, __nv_bfloat16* __restrict__ V_l) {
    extern __shared__ char smem[];
    const __nv_bfloat16 *Ah, *Al, *Bh, *Bl;
    const float* bias;
    __nv_bfloat16 *Ch, *Cl;
    switch (blockIdx.z) {
        case 0:  Ah = Aq_h; Al = Aq_l; Bh = Wq_h; Bl = Wq_l; bias = bq; Ch = Q_h; Cl = Q_l; break;
        case 1:  Ah = Av_h; Al = Av_l; Bh = Wk_h; Bl = Wk_l; bias = bk; Ch = K_h; Cl = K_l; break;
        default: Ah = Av_h; Al = Av_l; Bh = Wv_h; Bl = Wv_l; bias = bv; Ch = V_h; Cl = V_l; break;
    }
    float acc[4][4][4] = {};
    GEMM_BODY(acc)
    #pragma unroll
    for (int i = 0; i < 4; i++) {
        int row = m0 + wm * 64 + i * 16;
        #pragma unroll
        for (int j = 0; j < 4; j++) {
            int col = n0 + wn * 32 + j * 8 + 2 * q;
            float b0 = __ldg(bias + col);
            float b1 = __ldg(bias + col + 1);
            float vs[4] = {acc[i][j][0] + b0, acc[i][j][1] + b1,
                           acc[i][j][2] + b0, acc[i][j][3] + b1};
            u32 hb[4], lb[4];
            #pragma unroll
            for (int t = 0; t < 4; t++) {
                hb[t] = f2bf_bits(vs[t]);
                lb[t] = f2bf_bits(vs[t] - __uint_as_float(hb[t] << 16));
            }
            size_t o0 = (size_t)(row + g) * D_ + col;
            size_t o1 = (size_t)(row + g + 8) * D_ + col;
            *(u32*)&Ch[o0] = hb[0] | (hb[1] << 16);
            *(u32*)&Cl[o0] = lb[0] | (lb[1] << 16);
            *(u32*)&Ch[o1] = hb[2] | (hb[3] << 16);
            *(u32*)&Cl[o1] = lb[2] | (lb[3] << 16);
        }
    }
}

// ======================= flash attention (512 thr, QT=128) =================
#define QT 128
#define NCH 16
#define KROW 144
#define CTILE (128 * KROW)
#define CSTG  (2 * CTILE)
#define KB_OFF 0
#define VB_OFF (2 * CSTG)
#define QB_OFF (4 * CSTG)
#define FL_SMEM (QB_OFF + 2 * QT * KROW)
#define FT 512

__device__ __forceinline__ void fl_stage(u32 dst, const __nv_bfloat16* Xh,
                                         const __nv_bfloat16* Xl,
                                         int b, int h, int c, int tid) {
    #pragma unroll
    for (int i = tid; i < 2048; i += FT) {
        int which = i >> 10, j = i & 1023, row = j >> 3, sub = j & 7;
        const __nv_bfloat16* src = (which ? Xl : Xh) +
            ((size_t)b * S_ + (size_t)c * 128 + row) * D_ + h * KS_ + sub * 8;
        cp_async16(dst + which * CTILE + row * KROW + sub * 16, src);
    }
}

__global__ void __launch_bounds__(FT, 1) flash_attn(
    const __nv_bfloat16* __restrict__ Qh, const __nv_bfloat16* __restrict__ Ql,
    const __nv_bfloat16* __restrict__ Kh, const __nv_bfloat16* __restrict__ Kl,
    const __nv_bfloat16* __restrict__ Vh, const __nv_bfloat16* __restrict__ Vl,
    const float* __restrict__ mask, float* __restrict__ align,
    float* __restrict__ mu, float* __restrict__ mfin, float* __restrict__ isv,
    __nv_bfloat16* __restrict__ CtxH, __nv_bfloat16* __restrict__ CtxL) {
    extern __shared__ char smem[];
    const u32 sb = smem_u32(smem);

    const int tid = threadIdx.x, lane = tid & 31, w = tid >> 5;
    const int g = lane >> 2, qq = lane & 3;
    const int l7 = lane & 7, sel = lane >> 3;
    const int wr = w >> 1, wc = w & 1;
    const int bh = blockIdx.y, b = bh >> 4, h = bh & 15;
    const int q0 = blockIdx.x * QT;

    fl_stage(sb + QB_OFF, Qh, Ql, b, h, blockIdx.x, tid);
    fl_stage(sb + KB_OFF, Kh, Kl, b, h, 0, tid);
    fl_stage(sb + VB_OFF, Vh, Vl, b, h, 0, tid);
    cp_commit();

    u32 ahq[4][4], alq[4][4];
    float oacc[8][4] = {};
    float m0 = -3.0e38f, m1 = -3.0e38f, s0 = 0.f, s1 = 0.f;
    const float* mrow = mask + (size_t)b * S_ * S_;
    const int rloc0 = wr * 16 + g;
    const int rloc1 = rloc0 + 8;

    for (int c = 0; c < NCH; c++) {
        cp_wait<0>();
        __syncthreads();
        if (c + 1 < NCH) {
            u32 boff = ((c + 1) & 1) * CSTG;
            fl_stage(sb + KB_OFF + boff, Kh, Kl, b, h, c + 1, tid);
            fl_stage(sb + VB_OFF + boff, Vh, Vl, b, h, c + 1, tid);
            cp_commit();
        }

        if (c == 0) {
            const char* sQh = smem + QB_OFF;
            const char* sQl = sQh + QT * KROW;
            #pragma unroll
            for (int ks = 0; ks < 4; ks++) {
                int r0 = rloc0 * KROW, r1 = rloc1 * KROW;
                int c0 = (ks * 16 + 2 * qq) * 2, c1 = c0 + 16;
                ahq[ks][0] = *(const u32*)(sQh + r0 + c0);
                ahq[ks][1] = *(const u32*)(sQh + r1 + c0);
                ahq[ks][2] = *(const u32*)(sQh + r0 + c1);
                ahq[ks][3] = *(const u32*)(sQh + r1 + c1);
                alq[ks][0] = *(const u32*)(sQl + r0 + c0);
                alq[ks][1] = *(const u32*)(sQl + r1 + c0);
                alq[ks][2] = *(const u32*)(sQl + r0 + c1);
                alq[ks][3] = *(const u32*)(sQl + r1 + c1);
            }
        }

        u32 sKh_u = sb + KB_OFF + (c & 1) * CSTG;
        float sacc[8][4] = {};
        #pragma unroll
        for (int nb = 0; nb < 8; nb++) {
            u32 kb = sKh_u + (u32)((wc * 64 + nb * 8 + l7) * KROW
                     + (sel & 1) * 16 + (sel >> 1) * CTILE);
            #pragma unroll
            for (int ks = 0; ks < 4; ks++) {
                u32 b0, b1, l0, l1;
                ldsm_x4(b0, b1, l0, l1, kb + ks * 32);
                mma16816(sacc[nb], ahq[ks][0], ahq[ks][1], ahq[ks][2], ahq[ks][3], b0, b1);
                mma16816(sacc[nb], ahq[ks][0], ahq[ks][1], ahq[ks][2], ahq[ks][3], l0, l1);
                mma16816(sacc[nb], alq[ks][0], alq[ks][1], alq[ks][2], alq[ks][3], b0, b1);
            }
        }

        float mx0 = -3.0e38f, mx1 = -3.0e38f;
        #pragma unroll
        for (int nb = 0; nb < 8; nb++) {
            int col = c * 128 + wc * 64 + nb * 8 + 2 * qq;
            float2 mm0 = *(const float2*)&mrow[(size_t)(q0 + rloc0) * S_ + col];
            float2 mm1 = *(const float2*)&mrow[(size_t)(q0 + rloc1) * S_ + col];
            float v0 = sacc[nb][0] * 0.125f * mm0.x; if (v0 == 0.0f) v0 = NEG_BIG;
            float v1 = sacc[nb][1] * 0.125f * mm0.y; if (v1 == 0.0f) v1 = NEG_BIG;
            float v2 = sacc[nb][2] * 0.125f * mm1.x; if (v2 == 0.0f) v2 = NEG_BIG;
            float v3 = sacc[nb][3] * 0.125f * mm1.y; if (v3 == 0.0f) v3 = NEG_BIG;
            sacc[nb][0] = v0; sacc[nb][1] = v1; sacc[nb][2] = v2; sacc[nb][3] = v3;
            mx0 = fmaxf(mx0, fmaxf(v0, v1));
            mx1 = fmaxf(mx1, fmaxf(v2, v3));
        }
        mx0 = fmaxf(mx0, __shfl_xor_sync(0xffffffffu, mx0, 1));
        mx0 = fmaxf(mx0, __shfl_xor_sync(0xffffffffu, mx0, 2));
        mx1 = fmaxf(mx1, __shfl_xor_sync(0xffffffffu, mx1, 1));
        mx1 = fmaxf(mx1, __shfl_xor_sync(0xffffffffu, mx1, 2));

        float mn0 = fmaxf(m0, mx0), mn1 = fmaxf(m1, mx1);
        float f0 = exp_fast(m0 - mn0), f1 = exp_fast(m1 - mn1);
        m0 = mn0; m1 = mn1;
        s0 *= f0; s1 *= f1;
        if (qq == 0) {
            mu[((size_t)bh * S_ + q0 + rloc0) * (NCH * 2) + c * 2 + wc] = mn0;
            mu[((size_t)bh * S_ + q0 + rloc1) * (NCH * 2) + c * 2 + wc] = mn1;
        }
        #pragma unroll
        for (int nb2 = 0; nb2 < 8; nb2++) {
            oacc[nb2][0] *= f0; oacc[nb2][1] *= f0;
            oacc[nb2][2] *= f1; oacc[nb2][3] *= f1;
        }

        float ps0 = 0.f, ps1 = 0.f;
        u32 vb = sb + VB_OFF + (c & 1) * CSTG;
        #pragma unroll
        for (int kf = 0; kf < 4; kf++) {
            u32 pah[4], pal[4];
            #pragma unroll
            for (int half = 0; half < 2; half++) {
                int nb = kf * 2 + half;
                float p0 = exp_fast(sacc[nb][0] - m0);
                float p1 = exp_fast(sacc[nb][1] - m0);
                float p2 = exp_fast(sacc[nb][2] - m1);
                float p3 = exp_fast(sacc[nb][3] - m1);
                ps0 += p0 + p1; ps1 += p2 + p3;
                int col = c * 128 + wc * 64 + nb * 8 + 2 * qq;
                *(float2*)&align[((size_t)bh * S_ + q0 + rloc0) * S_ + col] = make_float2(p0, p1);
                *(float2*)&align[((size_t)bh * S_ + q0 + rloc1) * S_ + col] = make_float2(p2, p3);
                int sl = half * 2;
                pack_pair(p0, p1, pah[sl + 0], pal[sl + 0]);
                pack_pair(p2, p3, pah[sl + 1], pal[sl + 1]);
            }
            u32 vaddr = vb + (wc * 64 + kf * 16 + (lane & 15)) * KROW;
            #pragma unroll
            for (int nb2 = 0; nb2 < 8; nb2++) {
                u32 vh0, vh1, vl0, vl1;
                ldsm_x2_t(vh0, vh1, vaddr + nb2 * 16);
                ldsm_x2_t(vl0, vl1, vaddr + nb2 * 16 + CTILE);
                mma16816(oacc[nb2], pah[0], pah[1], pah[2], pah[3], vh0, vh1);
                mma16816(oacc[nb2], pah[0], pah[1], pah[2], pah[3], vl0, vl1);
                mma16816(oacc[nb2], pal[0], pal[1], pal[2], pal[3], vh0, vh1);
            }
        }
        ps0 += __shfl_xor_sync(0xffffffffu, ps0, 1);
        ps0 += __shfl_xor_sync(0xffffffffu, ps0, 2);
        ps1 += __shfl_xor_sync(0xffffffffu, ps1, 1);
        ps1 += __shfl_xor_sync(0xffffffffu, ps1, 2);
        s0 += ps0; s1 += ps1;
    }
    __syncthreads();

    // ---- epilogue: merge k-halves exactly ----
    float* part = (float*)smem;
    float* mh1  = part + 8192;
    float* sh1  = mh1 + 128;
    if (wc == 1) {
        #pragma unroll
        for (int nb2 = 0; nb2 < 8; nb2++) {
            int cc = nb2 * 8 + 2 * qq;
            *(float2*)&part[rloc0 * 64 + cc] = make_float2(oacc[nb2][0], oacc[nb2][1]);
            *(float2*)&part[rloc1 * 64 + cc] = make_float2(oacc[nb2][2], oacc[nb2][3]);
        }
        if (qq == 0) {
            mh1[rloc0] = m0; sh1[rloc0] = s0;
            mh1[rloc1] = m1; sh1[rloc1] = s1;
        }
    }
    __syncthreads();
    if (wc == 0) {
        float mo0 = mh1[rloc0], so0 = sh1[rloc0];
        float mo1 = mh1[rloc1], so1 = sh1[rloc1];
        float mf0 = fmaxf(m0, mo0), mf1 = fmaxf(m1, mo1);
        float fa0 = exp_fast(m0 - mf0), fb0 = exp_fast(mo0 - mf0);
        float fa1 = exp_fast(m1 - mf1), fb1 = exp_fast(mo1 - mf1);
        float inv0 = 1.0f / (s0 * fa0 + so0 * fb0);
        float inv1 = 1.0f / (s1 * fa1 + so1 * fb1);
        if (qq == 0) {
            size_t R0 = (size_t)bh * S_ + q0 + rloc0;
            size_t R1 = (size_t)bh * S_ + q0 + rloc1;
            mfin[R0] = mf0; isv[R0] = inv0;
            mfin[R1] = mf1; isv[R1] = inv1;
        }
        #pragma unroll
        for (int nb2 = 0; nb2 < 8; nb2++) {
            int cc = nb2 * 8 + 2 * qq;
            float2 a0 = *(const float2*)&part[rloc0 * 64 + cc];
            float2 a1 = *(const float2*)&part[rloc1 * 64 + cc];
            float o0 = (oacc[nb2][0] * fa0 + a0.x * fb0) * inv0;
            float o1 = (oacc[nb2][1] * fa0 + a0.y * fb0) * inv0;
            float o2 = (oacc[nb2][2] * fa1 + a1.x * fb1) * inv1;
            float o3 = (oacc[nb2][3] * fa1 + a1.y * fb1) * inv1;
            int col = h * KS_ + cc;
            size_t d0 = ((size_t)b * S_ + q0 + rloc0) * D_ + col;
            size_t d1 = ((size_t)b * S_ + q0 + rloc1) * D_ + col;
            u32 hb0, lb0, hb1, lb1;
            pack_pair(o0, o1, hb0, lb0);
            pack_pair(o2, o3, hb1, lb1);
            *(u32*)&CtxH[d0] = hb0;
            *(u32*)&CtxL[d0] = lb0;
            *(u32*)&CtxH[d1] = hb1;
            *(u32*)&CtxL[d1] = lb1;
        }
    }
}

// ---------------------------------------------------------------------------
extern "C" void kernel_launch(void* const* d_in, const int* in_sizes, int n_in,
                              void* d_out, int out_size) {
    const float* q    = (const float*)d_in[0];
    const float* v    = (const float*)d_in[1];
    const float* mask = (const float*)d_in[2];
    const float* wq_w = (const float*)d_in[3];
    const float* wq_b = (const float*)d_in[4];
    const float* wk_w = (const float*)d_in[5];
    const float* wk_b = (const float*)d_in[6];
    const float* wv_w = (const float*)d_in[7];
    const float* wv_b = (const float*)d_in[8];
    const float* wo_w = (const float*)d_in[9];
    const float* wo_b = (const float*)d_in[10];

    float* out = (float*)d_out;
    float* heads = out;
    float* align = out + NTOK;

    float* scratch = nullptr;
    cudaGetSymbolAddress((void**)&scratch, g_scratch);

    __nv_bfloat16* AqH = (__nv_bfloat16*)(scratch + 0 * F_ACT);
    __nv_bfloat16* AqL = (__nv_bfloat16*)(scratch + 1 * F_ACT);
    __nv_bfloat16* AvH = (__nv_bfloat16*)(scratch + 2 * F_ACT);
    __nv_bfloat16* AvL = (__nv_bfloat16*)(scratch + 3 * F_ACT);
    __nv_bfloat16* QsH = (__nv_bfloat16*)(scratch + 4 * F_ACT);
    __nv_bfloat16* QsL = (__nv_bfloat16*)(scratch + 5 * F_ACT);
    __nv_bfloat16* KsH = (__nv_bfloat16*)(scratch + 6 * F_ACT);
    __nv_bfloat16* KsL = (__nv_bfloat16*)(scratch + 7 * F_ACT);
    __nv_bfloat16* VsH = (__nv_bfloat16*)(scratch + 8 * F_ACT);
    __nv_bfloat16* VsL = (__nv_bfloat16*)(scratch + 9 * F_ACT);
    float* wb = scratch + 10 * F_ACT;
    __nv_bfloat16* WqH = (__nv_bfloat16*)(wb + 0 * F_W);
    __nv_bfloat16* WqL = (__nv_bfloat16*)(wb + 1 * F_W);
    __nv_bfloat16* WkH = (__nv_bfloat16*)(wb + 2 * F_W);
    __nv_bfloat16* WkL = (__nv_bfloat16*)(wb + 3 * F_W);
    __nv_bfloat16* WvH = (__nv_bfloat16*)(wb + 4 * F_W);
    __nv_bfloat16* WvL = (__nv_bfloat16*)(wb + 5 * F_W);
    __nv_bfloat16* WoH = (__nv_bfloat16*)(wb + 6 * F_W);
    __nv_bfloat16* WoL = (__nv_bfloat16*)(wb + 7 * F_W);

    float* mu_s = scratch + 2 * F_ACT;
    float* mf_s = scratch + 3 * F_ACT;
    float* is_s = mf_s + (size_t)B_ * H_ * S_;

    cudaFuncSetAttribute(gemm_mma, cudaFuncAttributeMaxDynamicSharedMemorySize, GSMEM);
    cudaFuncSetAttribute(gemm_split3, cudaFuncAttributeMaxDynamicSharedMemorySize, GSMEM);
    cudaFuncSetAttribute(flash_attn, cudaFuncAttributeMaxDynamicSharedMemorySize, FL_SMEM);

    int nAct = (int)NTOK;
    int gA = (nAct / 4 + 255) / 256;

    conv_w4<<<dim3(32, 32, 4), dim3(32, 8)>>>(wq_w, wk_w, wv_w, wo_w,
                                              WqH, WqL, WkH, WkL,
                                              WvH, WvL, WoH, WoL);
    conv_act2<<<dim3(gA, 1, 2), 256>>>(q, AqH, AqL, v, AvH, AvL, nAct);

    dim3 gproj3(D_ / 128, (B_ * S_) / 128, 3);
    gemm_split3<<<gproj3, 256, GSMEM>>>(AqH, AqL, AvH, AvL,
                                        WqH, WqL, WkH, WkL, WvH, WvL,
                                        wq_b, wk_b, wv_b,
                                        QsH, QsL, KsH, KsL, VsH, VsL);

    dim3 gfa(S_ / QT, B_ * H_);                   // (16, 32)
    flash_attn<<<gfa, FT, FL_SMEM>>>(QsH, QsL, KsH, KsL, VsH, VsL,
                                     mask, align, mu_s, mf_s, is_s, AqH, AqL);

    // output projection + fused align fixup
    dim3 gproj(D_ / 128, (B_ * S_) / 128);
    gemm_mma<<<gproj, 256, GSMEM>>>(AqH, AqL, WoH, WoL, wo_b, heads,
                                    align, mu_s, mf_s, is_s);
}

// round 17
// speedup vs baseline: 1.3440x; 1.3440x over previous
#include <cuda_runtime.h>
#include <cuda_bf16.h>
#include <cstdint>

#define B_  2
#define S_  2048
#define D_  1024
#define H_  16
#define KS_ 64
#define NEG_BIG (-1.0e9f)

#define NTOK ((size_t)B_ * S_ * D_)

#define F_ACT   (NTOK / 2)
#define F_W     ((size_t)D_ * D_ / 2)
__device__ __align__(16) float g_scratch[10 * F_ACT + 8 * F_W];

typedef uint32_t u32;

// ============================ helpers ======================================
__device__ __forceinline__ u32 smem_u32(const void* p) {
    u32 a;
    asm("{ .reg .u64 t; cvta.to.shared.u64 t, %1; cvt.u32.u64 %0, t; }"
        : "=r"(a) : "l"(p));
    return a;
}
__device__ __forceinline__ void cp_async16(u32 saddr, const void* gaddr) {
    asm volatile("cp.async.cg.shared.global [%0], [%1], 16;"
                 :: "r"(saddr), "l"(gaddr) : "memory");
}
__device__ __forceinline__ void cp_commit() {
    asm volatile("cp.async.commit_group;" ::: "memory");
}
template <int N>
__device__ __forceinline__ void cp_wait() {
    asm volatile("cp.async.wait_group %0;" :: "n"(N) : "memory");
}
__device__ __forceinline__ void mma16816(float* d, u32 a0, u32 a1,
                                         u32 a2, u32 a3, u32 b0, u32 b1) {
    asm volatile(
        "mma.sync.aligned.m16n8k16.row.col.f32.bf16.bf16.f32 "
        "{%0,%1,%2,%3}, {%4,%5,%6,%7}, {%8,%9}, {%0,%1,%2,%3};"
        : "+f"(d[0]), "+f"(d[1]), "+f"(d[2]), "+f"(d[3])
        : "r"(a0), "r"(a1), "r"(a2), "r"(a3), "r"(b0), "r"(b1));
}
__device__ __forceinline__ void ldsm_x2_t(u32& r0, u32& r1, u32 a) {
    asm volatile("ldmatrix.sync.aligned.m8n8.x2.trans.shared.b16 {%0,%1}, [%2];"
                 : "=r"(r0), "=r"(r1) : "r"(a));
}
__device__ __forceinline__ void ldsm_x4(u32& r0, u32& r1, u32& r2, u32& r3, u32 a) {
    asm volatile("ldmatrix.sync.aligned.m8n8.x4.shared.b16 {%0,%1,%2,%3}, [%4];"
                 : "=r"(r0), "=r"(r1), "=r"(r2), "=r"(r3) : "r"(a));
}
__device__ __forceinline__ u32 f2bf_bits(float x) {
    u32 u = __float_as_uint(x);
    return (u + 0x7FFFu + ((u >> 16) & 1u)) >> 16;
}
__device__ __forceinline__ void pack_pair(float p0, float p1, u32& hi, u32& lo) {
    asm("cvt.rn.bf16x2.f32 %0, %1, %2;" : "=r"(hi) : "f"(p1), "f"(p0));
    float h0 = __uint_as_float(hi << 16);
    float h1 = __uint_as_float(hi & 0xffff0000u);
    asm("cvt.rn.bf16x2.f32 %0, %1, %2;" : "=r"(lo) : "f"(p1 - h1), "f"(p0 - h0));
}
__device__ __forceinline__ float exp_fast(float x) {
    x = fmaxf(x, -87.3f);
    float y = x * 1.44269504089f;
    float n = rintf(y);
    float f = y - n;
    float p = 1.33336498402e-3f;
    p = fmaf(p, f, 9.61793571616e-3f);
    p = fmaf(p, f, 5.55043442248e-2f);
    p = fmaf(p, f, 2.40226506959e-1f);
    p = fmaf(p, f, 6.93147180560e-1f);
    p = fmaf(p, f, 1.0f);
    return __int_as_float(__float_as_int(p) + (((int)n) << 23));
}

// ======================= conversion kernels ================================
__global__ void conv_act2(const float* __restrict__ x0, __nv_bfloat16* __restrict__ h0,
                          __nv_bfloat16* __restrict__ l0,
                          const float* __restrict__ x1, __nv_bfloat16* __restrict__ h1,
                          __nv_bfloat16* __restrict__ l1, int n) {
    const float* x = blockIdx.z ? x1 : x0;
    __nv_bfloat16* h = blockIdx.z ? h1 : h0;
    __nv_bfloat16* l = blockIdx.z ? l1 : l0;
    int i = blockIdx.x * blockDim.x + threadIdx.x;
    int i4 = i * 4;
    if (i4 >= n) return;
    float4 v = *(const float4*)(x + i4);
    float vs[4] = {v.x, v.y, v.z, v.w};
    __nv_bfloat16 hh[4], ll[4];
    #pragma unroll
    for (int j = 0; j < 4; j++) {
        __nv_bfloat16 hi = __float2bfloat16_rn(vs[j]);
        float r = vs[j] - __bfloat162float(hi);
        hh[j] = hi;
        ll[j] = __float2bfloat16_rn(r);
    }
    __nv_bfloat162* H2 = (__nv_bfloat162*)(h + i4);
    __nv_bfloat162* L2 = (__nv_bfloat162*)(l + i4);
    H2[0] = __nv_bfloat162(hh[0], hh[1]);
    H2[1] = __nv_bfloat162(hh[2], hh[3]);
    L2[0] = __nv_bfloat162(ll[0], ll[1]);
    L2[1] = __nv_bfloat162(ll[2], ll[3]);
}

__global__ void conv_w4(const float* __restrict__ W0, const float* __restrict__ W1,
                        const float* __restrict__ W2, const float* __restrict__ W3,
                        __nv_bfloat16* __restrict__ T0h, __nv_bfloat16* __restrict__ T0l,
                        __nv_bfloat16* __restrict__ T1h, __nv_bfloat16* __restrict__ T1l,
                        __nv_bfloat16* __restrict__ T2h, __nv_bfloat16* __restrict__ T2l,
                        __nv_bfloat16* __restrict__ T3h, __nv_bfloat16* __restrict__ T3l) {
    __shared__ float t[32][33];
    const float* W;
    __nv_bfloat16 *Th, *Tl;
    switch (blockIdx.z) {
        case 0: W = W0; Th = T0h; Tl = T0l; break;
        case 1: W = W1; Th = T1h; Tl = T1l; break;
        case 2: W = W2; Th = T2h; Tl = T2l; break;
        default: W = W3; Th = T3h; Tl = T3l; break;
    }
    int n0 = blockIdx.x * 32, k0 = blockIdx.y * 32;
    int tx = threadIdx.x, ty = threadIdx.y;
    for (int r = ty; r < 32; r += 8)
        t[r][tx] = W[(size_t)(k0 + r) * D_ + n0 + tx];
    __syncthreads();
    for (int r = ty; r < 32; r += 8) {
        float x = t[tx][r];
        __nv_bfloat16 hi = __float2bfloat16_rn(x);
        float res = x - __bfloat162float(hi);
        size_t o = (size_t)(n0 + r) * D_ + k0 + tx;
        Th[o] = hi;
        Tl[o] = __float2bfloat16_rn(res);
    }
}

// ======================= HMMA GEMM core (ldsm fragments) ===================
#define GROW   80
#define GTILE  (128 * GROW)
#define GSTAGE (4 * GTILE)
#define GSMEM  (2 * GSTAGE)

#define GEMM_BODY(ACC)                                                          \
    const u32 sb = smem_u32(smem);                                              \
    const int tid  = threadIdx.x;                                               \
    const int lane = tid & 31;                                                  \
    const int wid  = tid >> 5;                                                  \
    const int wm   = wid >> 2;                                                  \
    const int wn   = wid & 3;                                                   \
    const int g    = lane >> 2;                                                 \
    const int q    = lane & 3;                                                  \
    const int l7   = lane & 7;                                                  \
    const int sel  = lane >> 3;                                                 \
    const int n0 = blockIdx.x * 128;                                            \
    const int m0 = blockIdx.y * 128;                                            \
    const int cid0 = tid * 2;                                                   \
    const int row0 = cid0 >> 2;                                                 \
    const int cc0  = (cid0 & 3) * 8;                                            \
    const int row1 = (cid0 + 1) >> 2;                                           \
    const int cc1  = ((cid0 + 1) & 3) * 8;                                      \
    const int NK = D_ / 32;                                                     \
    {                                                                           \
        u32 s = sb;                                                             \
        cp_async16(s + 0 * GTILE + row0 * GROW + (cc0 & 31) * 2, Ah + (size_t)(m0 + row0) * D_ + cc0); \
        cp_async16(s + 0 * GTILE + row1 * GROW + (cc1 & 31) * 2, Ah + (size_t)(m0 + row1) * D_ + cc1); \
        cp_async16(s + 1 * GTILE + row0 * GROW + (cc0 & 31) * 2, Al + (size_t)(m0 + row0) * D_ + cc0); \
        cp_async16(s + 1 * GTILE + row1 * GROW + (cc1 & 31) * 2, Al + (size_t)(m0 + row1) * D_ + cc1); \
        cp_async16(s + 2 * GTILE + row0 * GROW + (cc0 & 31) * 2, Bh + (size_t)(n0 + row0) * D_ + cc0); \
        cp_async16(s + 2 * GTILE + row1 * GROW + (cc1 & 31) * 2, Bh + (size_t)(n0 + row1) * D_ + cc1); \
        cp_async16(s + 3 * GTILE + row0 * GROW + (cc0 & 31) * 2, Bl + (size_t)(n0 + row0) * D_ + cc0); \
        cp_async16(s + 3 * GTILE + row1 * GROW + (cc1 & 31) * 2, Bl + (size_t)(n0 + row1) * D_ + cc1); \
        cp_commit();                                                            \
    }                                                                           \
    for (int ks = 0; ks < NK; ks++) {                                           \
        if (ks + 1 < NK) {                                                      \
            int k0 = (ks + 1) * 32;                                             \
            u32 s = sb + ((ks + 1) & 1) * GSTAGE;                               \
            cp_async16(s + 0 * GTILE + row0 * GROW + (cc0 & 31) * 2, Ah + (size_t)(m0 + row0) * D_ + k0 + cc0); \
            cp_async16(s + 0 * GTILE + row1 * GROW + (cc1 & 31) * 2, Ah + (size_t)(m0 + row1) * D_ + k0 + cc1); \
            cp_async16(s + 1 * GTILE + row0 * GROW + (cc0 & 31) * 2, Al + (size_t)(m0 + row0) * D_ + k0 + cc0); \
            cp_async16(s + 1 * GTILE + row1 * GROW + (cc1 & 31) * 2, Al + (size_t)(m0 + row1) * D_ + k0 + cc1); \
            cp_async16(s + 2 * GTILE + row0 * GROW + (cc0 & 31) * 2, Bh + (size_t)(n0 + row0) * D_ + k0 + cc0); \
            cp_async16(s + 2 * GTILE + row1 * GROW + (cc1 & 31) * 2, Bh + (size_t)(n0 + row1) * D_ + k0 + cc1); \
            cp_async16(s + 3 * GTILE + row0 * GROW + (cc0 & 31) * 2, Bl + (size_t)(n0 + row0) * D_ + k0 + cc0); \
            cp_async16(s + 3 * GTILE + row1 * GROW + (cc1 & 31) * 2, Bl + (size_t)(n0 + row1) * D_ + k0 + cc1); \
            cp_commit();                                                        \
            cp_wait<1>();                                                       \
        } else {                                                                \
            cp_wait<0>();                                                       \
        }                                                                       \
        __syncthreads();                                                        \
        u32 st_u  = sb + (ks & 1) * GSTAGE;                                     \
        u32 sAh_u = st_u;                                                       \
        u32 sBh_u = st_u + 2 * GTILE;                                           \
        _Pragma("unroll")                                                       \
        for (int kk = 0; kk < 32; kk += 16) {                                   \
            u32 bh[4][2], bl[4][2];                                             \
            _Pragma("unroll")                                                   \
            for (int j = 0; j < 4; j++) {                                       \
                u32 baddr = sBh_u + (u32)((wn * 32 + j * 8 + l7) * GROW         \
                            + (sel & 1) * 16 + (sel >> 1) * GTILE + kk * 2);    \
                ldsm_x4(bh[j][0], bh[j][1], bl[j][0], bl[j][1], baddr);         \
            }                                                                   \
            _Pragma("unroll")                                                   \
            for (int i = 0; i < 4; i++) {                                       \
                int m = wm * 64 + i * 16;                                       \
                u32 aaddr = sAh_u + (u32)((m + l7 + (sel & 1) * 8) * GROW       \
                            + (kk + (sel >> 1) * 8) * 2);                       \
                u32 ah0, ah1, ah2, ah3, al0, al1, al2, al3;                     \
                ldsm_x4(ah0, ah1, ah2, ah3, aaddr);                             \
                ldsm_x4(al0, al1, al2, al3, aaddr + GTILE);                     \
                _Pragma("unroll")                                               \
                for (int j = 0; j < 4; j++) {                                   \
                    mma16816(ACC[i][j], ah0, ah1, ah2, ah3, bh[j][0], bh[j][1]);\
                    mma16816(ACC[i][j], ah0, ah1, ah2, ah3, bl[j][0], bl[j][1]);\
                    mma16816(ACC[i][j], al0, al1, al2, al3, bh[j][0], bh[j][1]);\
                }                                                               \
            }                                                                   \
        }                                                                       \
        __syncthreads();                                                        \
    }

__global__ void __launch_bounds__(256) gemm_mma(
    const __nv_bfloat16* __restrict__ Ah, const __nv_bfloat16* __restrict__ Al,
    const __nv_bfloat16* __restrict__ Bh, const __nv_bfloat16* __restrict__ Bl,
    const float* __restrict__ bias, float* __restrict__ C) {
    extern __shared__ char smem[];
    float acc[4][4][4] = {};
    GEMM_BODY(acc)
    #pragma unroll
    for (int i = 0; i < 4; i++) {
        int row = m0 + wm * 64 + i * 16;
        #pragma unroll
        for (int j = 0; j < 4; j++) {
            int col = n0 + wn * 32 + j * 8 + 2 * q;
            float b0 = __ldg(bias + col);
            float b1 = __ldg(bias + col + 1);
            float2 v0 = make_float2(acc[i][j][0] + b0, acc[i][j][1] + b1);
            float2 v1 = make_float2(acc[i][j][2] + b0, acc[i][j][3] + b1);
            *(float2*)&C[(size_t)(row + g) * D_ + col]     = v0;
            *(float2*)&C[(size_t)(row + g + 8) * D_ + col] = v1;
        }
    }
}

__global__ void __launch_bounds__(256) gemm_split3(
    const __nv_bfloat16* __restrict__ Aq_h, const __nv_bfloat16* __restrict__ Aq_l,
    const __nv_bfloat16* __restrict__ Av_h, const __nv_bfloat16* __restrict__ Av_l,
    const __nv_bfloat16* __restrict__ Wq_h, const __nv_bfloat16* __restrict__ Wq_l,
    const __nv_bfloat16* __restrict__ Wk_h, const __nv_bfloat16* __restrict__ Wk_l,
    const __nv_bfloat16* __restrict__ Wv_h, const __nv_bfloat16* __restrict__ Wv_l,
    const float* __restrict__ bq, const float* __restrict__ bk, const float* __restrict__ bv,
    __nv_bfloat16* __restrict__ Q_h, __nv_bfloat16* __restrict__ Q_l,
    __nv_bfloat16* __restrict__ K_h, __nv_bfloat16* __restrict__ K_l,
    __nv_bfloat16* __restrict__ V_h, __nv_bfloat16* __restrict__ V_l) {
    extern __shared__ char smem[];
    const __nv_bfloat16 *Ah, *Al, *Bh, *Bl;
    const float* bias;
    __nv_bfloat16 *Ch, *Cl;
    switch (blockIdx.z) {
        case 0:  Ah = Aq_h; Al = Aq_l; Bh = Wq_h; Bl = Wq_l; bias = bq; Ch = Q_h; Cl = Q_l; break;
        case 1:  Ah = Av_h; Al = Av_l; Bh = Wk_h; Bl = Wk_l; bias = bk; Ch = K_h; Cl = K_l; break;
        default: Ah = Av_h; Al = Av_l; Bh = Wv_h; Bl = Wv_l; bias = bv; Ch = V_h; Cl = V_l; break;
    }
    float acc[4][4][4] = {};
    GEMM_BODY(acc)
    #pragma unroll
    for (int i = 0; i < 4; i++) {
        int row = m0 + wm * 64 + i * 16;
        #pragma unroll
        for (int j = 0; j < 4; j++) {
            int col = n0 + wn * 32 + j * 8 + 2 * q;
            float b0 = __ldg(bias + col);
            float b1 = __ldg(bias + col + 1);
            float vs[4] = {acc[i][j][0] + b0, acc[i][j][1] + b1,
                           acc[i][j][2] + b0, acc[i][j][3] + b1};
            u32 hb[4], lb[4];
            #pragma unroll
            for (int t = 0; t < 4; t++) {
                hb[t] = f2bf_bits(vs[t]);
                lb[t] = f2bf_bits(vs[t] - __uint_as_float(hb[t] << 16));
            }
            size_t o0 = (size_t)(row + g) * D_ + col;
            size_t o1 = (size_t)(row + g + 8) * D_ + col;
            *(u32*)&Ch[o0] = hb[0] | (hb[1] << 16);
            *(u32*)&Cl[o0] = lb[0] | (lb[1] << 16);
            *(u32*)&Ch[o1] = hb[2] | (hb[3] << 16);
            *(u32*)&Cl[o1] = lb[2] | (lb[3] << 16);
        }
    }
}

// ======================= flash attention (512 thr, QT=128) =================
#define QT 128
#define NCH 16
#define KROW 144
#define CTILE (128 * KROW)
#define CSTG  (2 * CTILE)
#define KB_OFF 0
#define VB_OFF (2 * CSTG)
#define QB_OFF (4 * CSTG)
#define FL_SMEM (QB_OFF + 2 * QT * KROW)
#define FT 512

__device__ __forceinline__ void fl_stage(u32 dst, const __nv_bfloat16* Xh,
                                         const __nv_bfloat16* Xl,
                                         int b, int h, int c, int tid) {
    #pragma unroll
    for (int i = tid; i < 2048; i += FT) {
        int which = i >> 10, j = i & 1023, row = j >> 3, sub = j & 7;
        const __nv_bfloat16* src = (which ? Xl : Xh) +
            ((size_t)b * S_ + (size_t)c * 128 + row) * D_ + h * KS_ + sub * 8;
        cp_async16(dst + which * CTILE + row * KROW + sub * 16, src);
    }
}

__global__ void __launch_bounds__(FT, 1) flash_attn(
    const __nv_bfloat16* __restrict__ Qh, const __nv_bfloat16* __restrict__ Ql,
    const __nv_bfloat16* __restrict__ Kh, const __nv_bfloat16* __restrict__ Kl,
    const __nv_bfloat16* __restrict__ Vh, const __nv_bfloat16* __restrict__ Vl,
    const float* __restrict__ mask, float* __restrict__ align,
    float* __restrict__ mu, float* __restrict__ mfin, float* __restrict__ isv,
    __nv_bfloat16* __restrict__ CtxH, __nv_bfloat16* __restrict__ CtxL) {
    extern __shared__ char smem[];
    const u32 sb = smem_u32(smem);

    const int tid = threadIdx.x, lane = tid & 31, w = tid >> 5;
    const int g = lane >> 2, qq = lane & 3;
    const int l7 = lane & 7, sel = lane >> 3;
    const int wr = w >> 1, wc = w & 1;
    const int bh = blockIdx.y, b = bh >> 4, h = bh & 15;
    const int q0 = blockIdx.x * QT;

    fl_stage(sb + QB_OFF, Qh, Ql, b, h, blockIdx.x, tid);
    fl_stage(sb + KB_OFF, Kh, Kl, b, h, 0, tid);
    fl_stage(sb + VB_OFF, Vh, Vl, b, h, 0, tid);
    cp_commit();

    u32 ahq[4][4], alq[4][4];
    float oacc[8][4] = {};
    float m0 = -3.0e38f, m1 = -3.0e38f, s0 = 0.f, s1 = 0.f;
    const float* mrow = mask + (size_t)b * S_ * S_;
    const int rloc0 = wr * 16 + g;
    const int rloc1 = rloc0 + 8;

    for (int c = 0; c < NCH; c++) {
        cp_wait<0>();
        __syncthreads();
        if (c + 1 < NCH) {
            u32 boff = ((c + 1) & 1) * CSTG;
            fl_stage(sb + KB_OFF + boff, Kh, Kl, b, h, c + 1, tid);
            fl_stage(sb + VB_OFF + boff, Vh, Vl, b, h, c + 1, tid);
            cp_commit();
        }

        if (c == 0) {
            const char* sQh = smem + QB_OFF;
            const char* sQl = sQh + QT * KROW;
            #pragma unroll
            for (int ks = 0; ks < 4; ks++) {
                int r0 = rloc0 * KROW, r1 = rloc1 * KROW;
                int c0 = (ks * 16 + 2 * qq) * 2, c1 = c0 + 16;
                ahq[ks][0] = *(const u32*)(sQh + r0 + c0);
                ahq[ks][1] = *(const u32*)(sQh + r1 + c0);
                ahq[ks][2] = *(const u32*)(sQh + r0 + c1);
                ahq[ks][3] = *(const u32*)(sQh + r1 + c1);
                alq[ks][0] = *(const u32*)(sQl + r0 + c0);
                alq[ks][1] = *(const u32*)(sQl + r1 + c0);
                alq[ks][2] = *(const u32*)(sQl + r0 + c1);
                alq[ks][3] = *(const u32*)(sQl + r1 + c1);
            }
        }

        u32 sKh_u = sb + KB_OFF + (c & 1) * CSTG;
        float sacc[8][4] = {};
        #pragma unroll
        for (int nb = 0; nb < 8; nb++) {
            u32 kb = sKh_u + (u32)((wc * 64 + nb * 8 + l7) * KROW
                     + (sel & 1) * 16 + (sel >> 1) * CTILE);
            #pragma unroll
            for (int ks = 0; ks < 4; ks++) {
                u32 b0, b1, l0, l1;
                ldsm_x4(b0, b1, l0, l1, kb + ks * 32);
                mma16816(sacc[nb], ahq[ks][0], ahq[ks][1], ahq[ks][2], ahq[ks][3], b0, b1);
                mma16816(sacc[nb], ahq[ks][0], ahq[ks][1], ahq[ks][2], ahq[ks][3], l0, l1);
                mma16816(sacc[nb], alq[ks][0], alq[ks][1], alq[ks][2], alq[ks][3], b0, b1);
            }
        }

        float mx0 = -3.0e38f, mx1 = -3.0e38f;
        #pragma unroll
        for (int nb = 0; nb < 8; nb++) {
            int col = c * 128 + wc * 64 + nb * 8 + 2 * qq;
            float2 mm0 = *(const float2*)&mrow[(size_t)(q0 + rloc0) * S_ + col];
            float2 mm1 = *(const float2*)&mrow[(size_t)(q0 + rloc1) * S_ + col];
            float v0 = sacc[nb][0] * 0.125f * mm0.x; if (v0 == 0.0f) v0 = NEG_BIG;
            float v1 = sacc[nb][1] * 0.125f * mm0.y; if (v1 == 0.0f) v1 = NEG_BIG;
            float v2 = sacc[nb][2] * 0.125f * mm1.x; if (v2 == 0.0f) v2 = NEG_BIG;
            float v3 = sacc[nb][3] * 0.125f * mm1.y; if (v3 == 0.0f) v3 = NEG_BIG;
            sacc[nb][0] = v0; sacc[nb][1] = v1; sacc[nb][2] = v2; sacc[nb][3] = v3;
            mx0 = fmaxf(mx0, fmaxf(v0, v1));
            mx1 = fmaxf(mx1, fmaxf(v2, v3));
        }
        mx0 = fmaxf(mx0, __shfl_xor_sync(0xffffffffu, mx0, 1));
        mx0 = fmaxf(mx0, __shfl_xor_sync(0xffffffffu, mx0, 2));
        mx1 = fmaxf(mx1, __shfl_xor_sync(0xffffffffu, mx1, 1));
        mx1 = fmaxf(mx1, __shfl_xor_sync(0xffffffffu, mx1, 2));

        float mn0 = fmaxf(m0, mx0), mn1 = fmaxf(m1, mx1);
        float f0 = exp_fast(m0 - mn0), f1 = exp_fast(m1 - mn1);
        m0 = mn0; m1 = mn1;
        s0 *= f0; s1 *= f1;
        if (qq == 0) {
            mu[((size_t)bh * S_ + q0 + rloc0) * (NCH * 2) + c * 2 + wc] = mn0;
            mu[((size_t)bh * S_ + q0 + rloc1) * (NCH * 2) + c * 2 + wc] = mn1;
        }
        #pragma unroll
        for (int nb2 = 0; nb2 < 8; nb2++) {
            oacc[nb2][0] *= f0; oacc[nb2][1] *= f0;
            oacc[nb2][2] *= f1; oacc[nb2][3] *= f1;
        }

        float ps0 = 0.f, ps1 = 0.f;
        u32 vb = sb + VB_OFF + (c & 1) * CSTG;
        #pragma unroll
        for (int kf = 0; kf < 4; kf++) {
            u32 pah[4], pal[4];
            #pragma unroll
            for (int half = 0; half < 2; half++) {
                int nb = kf * 2 + half;
                float p0 = exp_fast(sacc[nb][0] - m0);
                float p1 = exp_fast(sacc[nb][1] - m0);
                float p2 = exp_fast(sacc[nb][2] - m1);
                float p3 = exp_fast(sacc[nb][3] - m1);
                ps0 += p0 + p1; ps1 += p2 + p3;
                int col = c * 128 + wc * 64 + nb * 8 + 2 * qq;
                *(float2*)&align[((size_t)bh * S_ + q0 + rloc0) * S_ + col] = make_float2(p0, p1);
                *(float2*)&align[((size_t)bh * S_ + q0 + rloc1) * S_ + col] = make_float2(p2, p3);
                int sl = half * 2;
                pack_pair(p0, p1, pah[sl + 0], pal[sl + 0]);
                pack_pair(p2, p3, pah[sl + 1], pal[sl + 1]);
            }
            u32 vaddr = vb + (wc * 64 + kf * 16 + (lane & 15)) * KROW;
            #pragma unroll
            for (int nb2 = 0; nb2 < 8; nb2++) {
                u32 vh0, vh1, vl0, vl1;
                ldsm_x2_t(vh0, vh1, vaddr + nb2 * 16);
                ldsm_x2_t(vl0, vl1, vaddr + nb2 * 16 + CTILE);
                mma16816(oacc[nb2], pah[0], pah[1], pah[2], pah[3], vh0, vh1);
                mma16816(oacc[nb2], pah[0], pah[1], pah[2], pah[3], vl0, vl1);
                mma16816(oacc[nb2], pal[0], pal[1], pal[2], pal[3], vh0, vh1);
            }
        }
        ps0 += __shfl_xor_sync(0xffffffffu, ps0, 1);
        ps0 += __shfl_xor_sync(0xffffffffu, ps0, 2);
        ps1 += __shfl_xor_sync(0xffffffffu, ps1, 1);
        ps1 += __shfl_xor_sync(0xffffffffu, ps1, 2);
        s0 += ps0; s1 += ps1;
    }
    __syncthreads();

    // ---- epilogue: merge k-halves exactly ----
    float* part = (float*)smem;
    float* mh1  = part + 8192;
    float* sh1  = mh1 + 128;
    if (wc == 1) {
        #pragma unroll
        for (int nb2 = 0; nb2 < 8; nb2++) {
            int cc = nb2 * 8 + 2 * qq;
            *(float2*)&part[rloc0 * 64 + cc] = make_float2(oacc[nb2][0], oacc[nb2][1]);
            *(float2*)&part[rloc1 * 64 + cc] = make_float2(oacc[nb2][2], oacc[nb2][3]);
        }
        if (qq == 0) {
            mh1[rloc0] = m0; sh1[rloc0] = s0;
            mh1[rloc1] = m1; sh1[rloc1] = s1;
        }
    }
    __syncthreads();
    if (wc == 0) {
        float mo0 = mh1[rloc0], so0 = sh1[rloc0];
        float mo1 = mh1[rloc1], so1 = sh1[rloc1];
        float mf0 = fmaxf(m0, mo0), mf1 = fmaxf(m1, mo1);
        float fa0 = exp_fast(m0 - mf0), fb0 = exp_fast(mo0 - mf0);
        float fa1 = exp_fast(m1 - mf1), fb1 = exp_fast(mo1 - mf1);
        float inv0 = 1.0f / (s0 * fa0 + so0 * fb0);
        float inv1 = 1.0f / (s1 * fa1 + so1 * fb1);
        if (qq == 0) {
            size_t R0 = (size_t)bh * S_ + q0 + rloc0;
            size_t R1 = (size_t)bh * S_ + q0 + rloc1;
            mfin[R0] = mf0; isv[R0] = inv0;
            mfin[R1] = mf1; isv[R1] = inv1;
        }
        #pragma unroll
        for (int nb2 = 0; nb2 < 8; nb2++) {
            int cc = nb2 * 8 + 2 * qq;
            float2 a0 = *(const float2*)&part[rloc0 * 64 + cc];
            float2 a1 = *(const float2*)&part[rloc1 * 64 + cc];
            float o0 = (oacc[nb2][0] * fa0 + a0.x * fb0) * inv0;
            float o1 = (oacc[nb2][1] * fa0 + a0.y * fb0) * inv0;
            float o2 = (oacc[nb2][2] * fa1 + a1.x * fb1) * inv1;
            float o3 = (oacc[nb2][3] * fa1 + a1.y * fb1) * inv1;
            int col = h * KS_ + cc;
            size_t d0 = ((size_t)b * S_ + q0 + rloc0) * D_ + col;
            size_t d1 = ((size_t)b * S_ + q0 + rloc1) * D_ + col;
            u32 hb0, lb0, hb1, lb1;
            pack_pair(o0, o1, hb0, lb0);
            pack_pair(o2, o3, hb1, lb1);
            *(u32*)&CtxH[d0] = hb0;
            *(u32*)&CtxL[d0] = lb0;
            *(u32*)&CtxH[d1] = hb1;
            *(u32*)&CtxL[d1] = lb1;
        }
    }
}

// Normalize align: factor = exp(m_used[c][half] - m_final) / sum. 1 block/row.
__global__ void __launch_bounds__(256) fixup(
    float* __restrict__ align, const float* __restrict__ mu,
    const float* __restrict__ mfin, const float* __restrict__ isv) {
    size_t R = blockIdx.x;
    float mf = mfin[R];
    float is = isv[R];
    __shared__ float fac[NCH * 2];
    if (threadIdx.x < NCH * 2)
        fac[threadIdx.x] = exp_fast(mu[R * (NCH * 2) + threadIdx.x] - mf) * is;
    __syncthreads();
    float* row = align + R * S_;
    for (int i = threadIdx.x; i < S_ / 4; i += 256) {
        float f = fac[i >> 4];
        float4 v = *(float4*)&row[i * 4];
        v.x *= f; v.y *= f; v.z *= f; v.w *= f;
        *(float4*)&row[i * 4] = v;
    }
}

// ---------------------------------------------------------------------------
extern "C" void kernel_launch(void* const* d_in, const int* in_sizes, int n_in,
                              void* d_out, int out_size) {
    const float* q    = (const float*)d_in[0];
    const float* v    = (const float*)d_in[1];
    const float* mask = (const float*)d_in[2];
    const float* wq_w = (const float*)d_in[3];
    const float* wq_b = (const float*)d_in[4];
    const float* wk_w = (const float*)d_in[5];
    const float* wk_b = (const float*)d_in[6];
    const float* wv_w = (const float*)d_in[7];
    const float* wv_b = (const float*)d_in[8];
    const float* wo_w = (const float*)d_in[9];
    const float* wo_b = (const float*)d_in[10];

    float* out = (float*)d_out;
    float* heads = out;
    float* align = out + NTOK;

    float* scratch = nullptr;
    cudaGetSymbolAddress((void**)&scratch, g_scratch);

    __nv_bfloat16* AqH = (__nv_bfloat16*)(scratch + 0 * F_ACT);
    __nv_bfloat16* AqL = (__nv_bfloat16*)(scratch + 1 * F_ACT);
    __nv_bfloat16* AvH = (__nv_bfloat16*)(scratch + 2 * F_ACT);
    __nv_bfloat16* AvL = (__nv_bfloat16*)(scratch + 3 * F_ACT);
    __nv_bfloat16* QsH = (__nv_bfloat16*)(scratch + 4 * F_ACT);
    __nv_bfloat16* QsL = (__nv_bfloat16*)(scratch + 5 * F_ACT);
    __nv_bfloat16* KsH = (__nv_bfloat16*)(scratch + 6 * F_ACT);
    __nv_bfloat16* KsL = (__nv_bfloat16*)(scratch + 7 * F_ACT);
    __nv_bfloat16* VsH = (__nv_bfloat16*)(scratch + 8 * F_ACT);
    __nv_bfloat16* VsL = (__nv_bfloat16*)(scratch + 9 * F_ACT);
    float* wb = scratch + 10 * F_ACT;
    __nv_bfloat16* WqH = (__nv_bfloat16*)(wb + 0 * F_W);
    __nv_bfloat16* WqL = (__nv_bfloat16*)(wb + 1 * F_W);
    __nv_bfloat16* WkH = (__nv_bfloat16*)(wb + 2 * F_W);
    __nv_bfloat16* WkL = (__nv_bfloat16*)(wb + 3 * F_W);
    __nv_bfloat16* WvH = (__nv_bfloat16*)(wb + 4 * F_W);
    __nv_bfloat16* WvL = (__nv_bfloat16*)(wb + 5 * F_W);
    __nv_bfloat16* WoH = (__nv_bfloat16*)(wb + 6 * F_W);
    __nv_bfloat16* WoL = (__nv_bfloat16*)(wb + 7 * F_W);

    float* mu_s = scratch + 2 * F_ACT;
    float* mf_s = scratch + 3 * F_ACT;
    float* is_s = mf_s + (size_t)B_ * H_ * S_;

    cudaFuncSetAttribute(gemm_mma, cudaFuncAttributeMaxDynamicSharedMemorySize, GSMEM);
    cudaFuncSetAttribute(gemm_split3, cudaFuncAttributeMaxDynamicSharedMemorySize, GSMEM);
    cudaFuncSetAttribute(flash_attn, cudaFuncAttributeMaxDynamicSharedMemorySize, FL_SMEM);

    int nAct = (int)NTOK;
    int gA = (nAct / 4 + 255) / 256;

    conv_w4<<<dim3(32, 32, 4), dim3(32, 8)>>>(wq_w, wk_w, wv_w, wo_w,
                                              WqH, WqL, WkH, WkL,
                                              WvH, WvL, WoH, WoL);
    conv_act2<<<dim3(gA, 1, 2), 256>>>(q, AqH, AqL, v, AvH, AvL, nAct);

    dim3 gproj3(D_ / 128, (B_ * S_) / 128, 3);
    gemm_split3<<<gproj3, 256, GSMEM>>>(AqH, AqL, AvH, AvL,
                                        WqH, WqL, WkH, WkL, WvH, WvL,
                                        wq_b, wk_b, wv_b,
                                        QsH, QsL, KsH, KsL, VsH, VsL);

    dim3 gfa(S_ / QT, B_ * H_);                   // (16, 32)
    flash_attn<<<gfa, FT, FL_SMEM>>>(QsH, QsL, KsH, KsL, VsH, VsL,
                                     mask, align, mu_s, mf_s, is_s, AqH, AqL);

    // ---- fork: fixup (DRAM-bound) runs concurrently with gemm_mma (tensor) --
    {
        cudaStream_t s2;
        cudaStreamCreateWithFlags(&s2, cudaStreamNonBlocking);
        cudaEvent_t evFork, evJoin;
        cudaEventCreateWithFlags(&evFork, cudaEventDisableTiming);
        cudaEventCreateWithFlags(&evJoin, cudaEventDisableTiming);

        cudaEventRecord(evFork, 0);               // after flash_attn
        cudaStreamWaitEvent(s2, evFork, 0);
        fixup<<<B_ * H_ * S_, 256, 0, s2>>>(align, mu_s, mf_s, is_s);
        cudaEventRecord(evJoin, s2);

        dim3 gproj(D_ / 128, (B_ * S_) / 128);
        gemm_mma<<<gproj, 256, GSMEM>>>(AqH, AqL, WoH, WoL, wo_b, heads);

        cudaStreamWaitEvent(0, evJoin, 0);        // join before harness ops
    }
}